// round 6
// baseline (speedup 1.0000x reference)
#include <cuda_runtime.h>
#include <math_constants.h>

// Morphological opening (10x10 min then 10x10 max, SAME pad lo=4/hi=5),
// NHWC [16,512,512,8] f32. Fused, vertical-first, van Herk windows.
// Block = 32(h) x 64(w) tile x ALL 8 channels. Tasks at float2 granularity
// so 1024 threads/block fit in 64 regs -> 32 warps/SM (2x round 5).
// Stages: V1 gmem->B (fused vertical min, coalesced), H1 B->E (min+mask),
//         H2 E->F (max, F overlays B), V2 F->gmem (max, coalesced).

#define H_   512
#define W_   512
#define TH   32
#define TW   64
#define NT   1024

#define NE    41             // eroded row range (TH + 9)
#define NCB   82             // input cols covered (TW + 18)
#define NCE   73             // eroded cols with dilation halo (TW + 9)
#define QF    4              // float2 quarters per pixel (8 channels)

#define B_F2  (NCB * QF * NE)   // 13448
#define E_F2  (NCE * QF * NE)   // 11972
#define B_OFF 0
#define E_OFF B_F2
#define F_OFF 0                 // F: 256*41 = 10496 <= 13448, overlays B
#define SMEM_F2 (B_F2 + E_F2)   // 25420
#define SMEM_BYTES (SMEM_F2 * 8)  // 203,360

__device__ __forceinline__ float2 min2(float2 a, float2 b) {
    return make_float2(fminf(a.x,b.x), fminf(a.y,b.y));
}
__device__ __forceinline__ float2 max2(float2 a, float2 b) {
    return make_float2(fmaxf(a.x,b.x), fmaxf(a.y,b.y));
}

__global__ __launch_bounds__(NT, 1)
void opening_kernel(const float2* __restrict__ in2, float2* __restrict__ out2) {
    extern __shared__ float2 sm[];
    float2* Bs = sm + B_OFF;   // B[cF][e], cF = cb*4+q in [0,328)
    float2* Es = sm + E_OFF;   // E[cF'][e], cF' = c'*4+q in [0,292)
    float2* Fs = sm + F_OFF;   // F[cF''][e], cF'' = c''*4+q in [0,256)

    const int b   = blockIdx.z;
    const int gh0 = blockIdx.y * TH;
    const int gw0 = blockIdx.x * TW;
    const int tid = threadIdx.x;

    const size_t chanBase = (size_t)b * H_ * W_ * QF;   // f2 units
    const float2 INF2  = make_float2( CUDART_INF_F,  CUDART_INF_F);
    const float2 NINF2 = make_float2(-CUDART_INF_F, -CUDART_INF_F);

    // ---- V1: vertical min fused with coalesced gmem load. 328x5 = 1640. ----
    #pragma unroll 1
    for (int i = tid; i < 328 * 5; i += NT) {
        int cF  = i % 328, seg = i / 328;
        int e0  = seg * 9;
        int n   = (seg == 4) ? 5 : 9;
        int cb  = cF >> 2;
        int gc  = gw0 + cb - 8;
        bool colOK = ((unsigned)gc < W_);
        const float2* src = in2 + chanBase + (size_t)(gw0 - 8) * QF + cF;
        int grBase = gh0 - 8 + e0;

        float2 x[10];
        #pragma unroll
        for (int t = 0; t < 10; t++) {
            int gr = grBase + t;
            x[t] = (colOK && (unsigned)gr < H_) ? src[(size_t)gr * (W_ * QF)] : INF2;
        }
        #pragma unroll
        for (int j = 8; j >= 0; j--) x[j] = min2(x[j], x[j+1]);
        float2 pr = x[9];
        float2* q = Bs + cF * NE + e0;
        q[0] = x[0];
        #pragma unroll
        for (int j = 1; j < 9; j++) {
            if (j >= n) break;
            int gr = grBase + 9 + j;
            float2 xn = (colOK && (unsigned)gr < H_) ? src[(size_t)gr * (W_ * QF)] : INF2;
            pr = min2(pr, xn);
            q[j] = min2(x[j], pr);
        }
    }
    __syncthreads();

    // ---- H1: horizontal min B -> eroded E, mask -inf off-image. 41*4*9=1476 ----
    #pragma unroll 1
    for (int i = tid; i < 41 * QF * 9; i += NT) {
        int e   = i % 41;
        int t2  = i / 41;          // 0..35
        int qd  = t2 & 3;
        int seg = t2 >> 2;         // 0..8
        int c0  = seg * 9;
        int n   = (seg == 8) ? 1 : 9;
        const float2* p = Bs + (c0 * QF + qd) * NE + e;   // step 4*NE per col
        float2 x[10];
        #pragma unroll
        for (int t = 0; t < 10; t++) x[t] = p[t * (QF * NE)];
        #pragma unroll
        for (int j = 8; j >= 0; j--) x[j] = min2(x[j], x[j+1]);
        float2 pr = x[9];
        bool rowOK = ((unsigned)(gh0 + e - 4) < H_);
        float2* q = Es + (c0 * QF + qd) * NE + e;
        q[0] = (rowOK && (unsigned)(gw0 + c0 - 4) < W_) ? x[0] : NINF2;
        #pragma unroll
        for (int j = 1; j < 9; j++) {
            if (j >= n) break;
            pr = min2(pr, p[(9 + j) * (QF * NE)]);
            float2 v = min2(x[j], pr);
            if (!rowOK || (unsigned)(gw0 + c0 + j - 4) >= W_) v = NINF2;
            q[j * (QF * NE)] = v;
        }
    }
    __syncthreads();

    // ---- H2: horizontal max E -> F. 41*4*8 = 1312 tasks. ----
    #pragma unroll 1
    for (int i = tid; i < 41 * QF * 8; i += NT) {
        int e   = i % 41;
        int t2  = i / 41;          // 0..31
        int qd  = t2 & 3;
        int seg = t2 >> 2;         // 0..7
        int c0  = seg * 9;
        int n   = (seg == 7) ? 1 : 9;
        const float2* p = Es + (c0 * QF + qd) * NE + e;
        float2 x[10];
        #pragma unroll
        for (int t = 0; t < 10; t++) x[t] = p[t * (QF * NE)];
        #pragma unroll
        for (int j = 8; j >= 0; j--) x[j] = max2(x[j], x[j+1]);
        float2 pr = x[9];
        float2* q = Fs + (c0 * QF + qd) * NE + e;
        q[0] = x[0];
        #pragma unroll
        for (int j = 1; j < 9; j++) {
            if (j >= n) break;
            pr = max2(pr, p[(9 + j) * (QF * NE)]);
            q[j * (QF * NE)] = max2(x[j], pr);
        }
    }
    __syncthreads();

    // ---- V2: vertical max F -> gmem (coalesced). 256 x 4 segs = 1024. ----
    {
        int i   = tid;
        int cF  = i % 256, seg = i / 256;
        int r0  = seg * 8;
        const float2* p = Fs + cF * NE + r0;   // stride 1 along e
        float2 x[10];
        #pragma unroll
        for (int t = 0; t < 10; t++) x[t] = p[t];
        #pragma unroll
        for (int j = 8; j >= 0; j--) x[j] = max2(x[j], x[j+1]);
        float2 pr = x[9];
        float2* q = out2 + chanBase + ((size_t)(gh0 + r0) * W_ + gw0) * QF + cF;
        q[0] = x[0];
        #pragma unroll
        for (int j = 1; j < 8; j++) {
            pr = max2(pr, p[9 + j]);
            q[(size_t)j * (W_ * QF)] = max2(x[j], pr);
        }
    }
}

extern "C" void kernel_launch(void* const* d_in, const int* in_sizes, int n_in,
                              void* d_out, int out_size) {
    const float2* in  = (const float2*)d_in[0];
    float2* out = (float2*)d_out;

    cudaFuncSetAttribute(opening_kernel,
                         cudaFuncAttributeMaxDynamicSharedMemorySize, SMEM_BYTES);

    dim3 grid(W_ / TW, H_ / TH, 16);
    opening_kernel<<<grid, NT, SMEM_BYTES>>>(in, out);
}

// round 7
// speedup vs baseline: 1.4537x; 1.4537x over previous
#include <cuda_runtime.h>
#include <math_constants.h>

// Morphological opening (10x10 min then 10x10 max, SAME pad lo=4/hi=5),
// NHWC [16,512,512,8] f32. Fused, vertical-first, van Herk windows.
// Block = 16(h) x 32(w) tile x ALL 8 channels (float4 granularity, coalesced
// gmem). Smem 72.8KB -> 3 blocks/SM so barriers overlap across blocks.
// Stages: V1 gmem->B (vertical min fused with load), H1 B->E (min + mask),
//         H2 E->F (max, F overlays B), V2 F->gmem (max).

#define H_   512
#define W_   512
#define TH   16
#define TW   32
#define NT   256

#define NE    25             // eroded row range (TH + 9)
#define NCB   50             // input cols covered (TW + 18)
#define NCE   41             // eroded cols with dilation halo (TW + 9)

#define BCF   (NCB * 2)      // 100 fused (col,half) B columns
#define ECF   (NCE * 2)      // 82 fused E columns
#define FCF   (TW * 2)       // 64 fused F columns

#define B_OFF 0
#define E_OFF (BCF * NE)                 // 2500
#define F_OFF 0                          // F: 64*25=1600 <= 2500, overlays B
#define SMEM_F4 (E_OFF + ECF * NE)       // 4550
#define SMEM_BYTES (SMEM_F4 * 16)        // 72,800

__device__ __forceinline__ float4 min4(float4 a, float4 b) {
    return make_float4(fminf(a.x,b.x), fminf(a.y,b.y), fminf(a.z,b.z), fminf(a.w,b.w));
}
__device__ __forceinline__ float4 max4(float4 a, float4 b) {
    return make_float4(fmaxf(a.x,b.x), fmaxf(a.y,b.y), fmaxf(a.z,b.z), fmaxf(a.w,b.w));
}

__global__ __launch_bounds__(NT, 3)
void opening_kernel(const float4* __restrict__ in4, float4* __restrict__ out4) {
    extern __shared__ float4 sm[];
    float4* Bs = sm + B_OFF;   // B[cF][e], cF = cb*2+h
    float4* Es = sm + E_OFF;   // E[cF'][e]
    float4* Fs = sm + F_OFF;   // F[cF''][e]

    const int b   = blockIdx.z;
    const int gh0 = blockIdx.y * TH;
    const int gw0 = blockIdx.x * TW;
    const int tid = threadIdx.x;

    const size_t chanBase = (size_t)b * H_ * W_ * 2;   // f4 units
    const float4 INF4  = make_float4( CUDART_INF_F,  CUDART_INF_F,  CUDART_INF_F,  CUDART_INF_F);
    const float4 NINF4 = make_float4(-CUDART_INF_F, -CUDART_INF_F, -CUDART_INF_F, -CUDART_INF_F);

    // ---- V1: vertical min fused with coalesced gmem load. 100 x 3 = 300. ----
    // B[cF][e] = min over input rows gh0+e-8 .. gh0+e+1 at fused col cF.
    #pragma unroll 1
    for (int i = tid; i < BCF * 3; i += NT) {
        int cF  = i % BCF, seg = i / BCF;
        int e0  = seg * 9;
        int n   = (seg == 2) ? 7 : 9;
        int cb  = cF >> 1;
        int gc  = gw0 + cb - 8;
        bool colOK = ((unsigned)gc < W_);
        const float4* src = in4 + chanBase + (size_t)(gw0 - 8) * 2 + cF;
        int grBase = gh0 - 8 + e0;

        float4 x[10];
        #pragma unroll
        for (int t = 0; t < 10; t++) {
            int gr = grBase + t;
            x[t] = (colOK && (unsigned)gr < H_) ? src[(size_t)gr * (W_ * 2)] : INF4;
        }
        #pragma unroll
        for (int j = 8; j >= 0; j--) x[j] = min4(x[j], x[j+1]);
        float4 pr = x[9];
        float4* q = Bs + cF * NE + e0;
        q[0] = x[0];
        #pragma unroll
        for (int j = 1; j < 9; j++) {
            if (j >= n) break;
            int gr = grBase + 9 + j;
            float4 xn = (colOK && (unsigned)gr < H_) ? src[(size_t)gr * (W_ * 2)] : INF4;
            pr = min4(pr, xn);
            q[j] = min4(x[j], pr);
        }
    }
    __syncthreads();

    // ---- H1: horizontal min B -> eroded E, mask -inf off-image. 25*2*5=250 ----
    if (tid < 25 * 2 * 5) {
        int e   = tid % NE;
        int t2  = tid / NE;        // 0..9
        int h   = t2 & 1;
        int seg = t2 >> 1;         // 0..4
        int c0  = seg * 9;
        int n   = (seg == 4) ? 5 : 9;
        const float4* p = Bs + (c0 * 2 + h) * NE + e;   // col step 2*NE
        float4 x[10];
        #pragma unroll
        for (int t = 0; t < 10; t++) x[t] = p[t * (2 * NE)];
        #pragma unroll
        for (int j = 8; j >= 0; j--) x[j] = min4(x[j], x[j+1]);
        float4 pr = x[9];
        bool rowOK = ((unsigned)(gh0 + e - 4) < H_);
        float4* q = Es + (c0 * 2 + h) * NE + e;
        q[0] = (rowOK && (unsigned)(gw0 + c0 - 4) < W_) ? x[0] : NINF4;
        #pragma unroll
        for (int j = 1; j < 9; j++) {
            if (j >= n) break;
            pr = min4(pr, p[(9 + j) * (2 * NE)]);
            float4 v = min4(x[j], pr);
            if (!rowOK || (unsigned)(gw0 + c0 + j - 4) >= W_) v = NINF4;
            q[j * (2 * NE)] = v;
        }
    }
    __syncthreads();

    // ---- H2: horizontal max E -> F. 25*2*4 = 200 tasks. ----
    if (tid < 25 * 2 * 4) {
        int e   = tid % NE;
        int t2  = tid / NE;        // 0..7
        int h   = t2 & 1;
        int seg = t2 >> 1;         // 0..3
        int c0  = seg * 9;
        int n   = (seg == 3) ? 5 : 9;
        const float4* p = Es + (c0 * 2 + h) * NE + e;
        float4 x[10];
        #pragma unroll
        for (int t = 0; t < 10; t++) x[t] = p[t * (2 * NE)];
        #pragma unroll
        for (int j = 8; j >= 0; j--) x[j] = max4(x[j], x[j+1]);
        float4 pr = x[9];
        float4* q = Fs + (c0 * 2 + h) * NE + e;
        q[0] = x[0];
        #pragma unroll
        for (int j = 1; j < 9; j++) {
            if (j >= n) break;
            pr = max4(pr, p[(9 + j) * (2 * NE)]);
            q[j * (2 * NE)] = max4(x[j], pr);
        }
    }
    __syncthreads();

    // ---- V2: vertical max F -> gmem (coalesced). 64 x 2 segs = 128. ----
    if (tid < FCF * 2) {
        int cF  = tid % FCF, seg = tid / FCF;
        int r0  = seg * 9;
        int n   = (seg == 1) ? 7 : 9;
        const float4* p = Fs + cF * NE + r0;   // stride 1 along e
        float4 x[10];
        #pragma unroll
        for (int t = 0; t < 10; t++) x[t] = p[t];
        #pragma unroll
        for (int j = 8; j >= 0; j--) x[j] = max4(x[j], x[j+1]);
        float4 pr = x[9];
        float4* q = out4 + chanBase + ((size_t)(gh0 + r0) * W_ + gw0) * 2 + cF;
        q[0] = x[0];
        #pragma unroll
        for (int j = 1; j < 9; j++) {
            if (j >= n) break;
            pr = max4(pr, p[9 + j]);
            q[(size_t)j * (W_ * 2)] = max4(x[j], pr);
        }
    }
}

extern "C" void kernel_launch(void* const* d_in, const int* in_sizes, int n_in,
                              void* d_out, int out_size) {
    const float4* in  = (const float4*)d_in[0];
    float4* out = (float4*)d_out;

    cudaFuncSetAttribute(opening_kernel,
                         cudaFuncAttributeMaxDynamicSharedMemorySize, SMEM_BYTES);

    dim3 grid(W_ / TW, H_ / TH, 16);
    opening_kernel<<<grid, NT, SMEM_BYTES>>>(in, out);
}